// round 3
// baseline (speedup 1.0000x reference)
#include <cuda_runtime.h>
#include <cstdint>

// Inv1x1MM_SVD, C=16, 65536 positions. 16 lanes per position, lane j owns
// column j in packed f32x2 registers. MGS with column-k broadcast via shared
// memory (stored once by lane k together with 1/||c_k||^2). Norms are
// recomputed FRESH each step (incremental tracking blows up on the
// worst-conditioned of the 131072 random matrices).

constexpr int NPOS = 8 * 8192;
constexpr int PSTRIDE = 528;
constexpr int POS_PER_BLOCK = 16;      // 256 threads
constexpr int BUFF = 336;              // floats per position buffer

#define FMA2(d, a, b, c) asm("fma.rn.f32x2 %0, %1, %2, %3;" : "=l"(d) : "l"(a), "l"(b), "l"(c))
#define MUL2(d, a, b)    asm("mul.rn.f32x2 %0, %1, %2;"     : "=l"(d) : "l"(a), "l"(b))
#define PACK2(d, lo, hi) asm("mov.b64 %0, {%1, %2};"        : "=l"(d) : "f"(lo), "f"(hi))
#define UNPACK2(lo, hi, d) asm("mov.b64 {%0, %1}, %2;" : "=f"(lo), "=f"(hi) : "l"(d))

__device__ __forceinline__ uint32_t smem_u32(const void* p) {
    uint32_t a;
    asm("{ .reg .u64 t; cvta.to.shared.u64 t, %1; cvt.u32.u64 %0, t; }" : "=r"(a) : "l"(p));
    return a;
}
__device__ __forceinline__ void lds2(uint64_t& a, uint64_t& b, uint32_t addr) {
    asm volatile("ld.shared.v2.u64 {%0, %1}, [%2];" : "=l"(a), "=l"(b) : "r"(addr));
}
__device__ __forceinline__ void sts2(uint32_t addr, uint64_t a, uint64_t b) {
    asm volatile("st.shared.v2.u64 [%0], {%1, %2};" :: "r"(addr), "l"(a), "l"(b) : "memory");
}
__device__ __forceinline__ float ldsf(uint32_t addr) {
    float v;
    asm volatile("ld.shared.f32 %0, [%1];" : "=f"(v) : "r"(addr));
    return v;
}
__device__ __forceinline__ void stsf(uint32_t addr, float v) {
    asm volatile("st.shared.f32 [%0], %1;" :: "r"(addr), "f"(v) : "memory");
}

// dot of two packed 16-vectors -> scalar
__device__ __forceinline__ float dot16(const uint64_t (&a)[8], const uint64_t (&b)[8]) {
    uint64_t acc;
    MUL2(acc, a[0], b[0]);
    #pragma unroll
    for (int i = 1; i < 8; i++) FMA2(acc, a[i], b[i], acc);
    float lo, hi;
    UNPACK2(lo, hi, acc);
    return lo + hi;
}

__device__ __forceinline__ void load16(uint64_t (&q)[8], uint32_t addr) {
    lds2(q[0], q[1], addr);
    lds2(q[2], q[3], addr + 16);
    lds2(q[4], q[5], addr + 32);
    lds2(q[6], q[7], addr + 48);
}
__device__ __forceinline__ void store_col(uint32_t addr, const uint64_t (&c)[8], float inv) {
    sts2(addr,      c[0], c[1]);
    sts2(addr + 16, c[2], c[3]);
    sts2(addr + 32, c[4], c[5]);
    sts2(addr + 48, c[6], c[7]);
    stsf(addr + 64, inv);
}

// MGS over 16 distributed columns. On exit: c = unnormalized orthogonal
// column j, nrm = ||c||^2 (fresh).
__device__ __forceinline__ void mgs16(uint64_t (&c)[8], float& nrm, uint32_t base, int j) {
    nrm = dot16(c, c);
    if (j == 0) store_col(base, c, __fdividef(1.0f, fmaxf(nrm, 1e-35f)));
    #pragma unroll 1
    for (int k = 0; k < 15; k++) {
        __syncwarp();
        const uint32_t ca = base + (uint32_t)k * 80u;
        uint64_t q[8];
        load16(q, ca);
        const float invqn = ldsf(ca + 64);
        const float d = dot16(q, c);
        const float scale = (j > k) ? d * invqn : 0.0f;
        uint64_t ns2;
        const float ns = -scale;
        PACK2(ns2, ns, ns);
        #pragma unroll
        for (int i = 0; i < 8; i++) FMA2(c[i], ns2, q[i], c[i]);
        nrm = dot16(c, c);  // FRESH norm (stability on ill-conditioned inputs)
        if (j == k + 1)
            store_col(base + (uint32_t)j * 80u, c, __fdividef(1.0f, fmaxf(nrm, 1e-35f)));
    }
}

__global__ void __launch_bounds__(256)
inv1x1mm_svd_kernel(const float* __restrict__ data,
                    const float* __restrict__ paras,
                    float* __restrict__ out) {
    __shared__ __align__(16) float sm[POS_PER_BLOCK * BUFF];

    const int tid = threadIdx.x;
    const int pb  = tid >> 4;          // position within block (0..15)
    const int j   = tid & 15;          // column index
    const int pos = blockIdx.x * POS_PER_BLOCK + pb;

    const float* p = paras + (size_t)pos * PSTRIDE;
    const uint32_t base = smem_u32(&sm[pb * BUFF]);

    const float dval = __ldg(&data[pos * 16 + j]);
    const float ls   = __ldg(&p[j]);
    stsf(base + 1280u + (uint32_t)j * 4u, dval);  // data vector slot

    // ---- QR of U: lane j loads column j, packed in row pairs ----
    uint64_t c[8];
    #pragma unroll
    for (int i = 0; i < 8; i++) {
        const float lo = __ldg(&p[16 + (2 * i) * 16 + j]);
        const float hi = __ldg(&p[16 + (2 * i + 1) * 16 + j]);
        PACK2(c[i], lo, hi);
    }
    float nrm0;
    mgs16(c, nrm0, base, j);

    // v_j = (data . q0_j) / ||q0_j||;  w_j = v_j * exp(ls_j)
    uint64_t dv[8];
    load16(dv, base + 1280u);
    const float v = dot16(dv, c) * rsqrtf(fmaxf(nrm0, 1e-35f));
    const float w = v * __expf(ls);

    // ---- QR of V ----
    #pragma unroll
    for (int i = 0; i < 8; i++) {
        const float lo = __ldg(&p[272 + (2 * i) * 16 + j]);
        const float hi = __ldg(&p[272 + (2 * i + 1) * 16 + j]);
        PACK2(c[i], lo, hi);
    }
    float nrm1;
    mgs16(c, nrm1, base, j);

    // res_d = sum_j w'_j * q1col_j[d]  with w'_j = w_j / ||q1_j||
    const float wj = w * rsqrtf(fmaxf(nrm1, 1e-35f));
    uint64_t w2;
    PACK2(w2, wj, wj);
    #pragma unroll
    for (int i = 0; i < 8; i++) MUL2(c[i], w2, c[i]);

    __syncwarp();  // all reads of the QR2 column cache are done
    const uint32_t myslot = base + (uint32_t)j * 80u;
    sts2(myslot,      c[0], c[1]);
    sts2(myslot + 16, c[2], c[3]);
    sts2(myslot + 32, c[4], c[5]);
    sts2(myslot + 48, c[6], c[7]);
    __syncwarp();

    // lane j accumulates output element d=j: row j across the 16 stored columns
    float acc = 0.0f;
    #pragma unroll
    for (int jj = 0; jj < 16; jj++)
        acc += ldsf(base + (uint32_t)jj * 80u + (uint32_t)j * 4u);

    out[pos * 16 + j] = acc;
}

extern "C" void kernel_launch(void* const* d_in, const int* in_sizes, int n_in,
                              void* d_out, int out_size) {
    const float* data  = (const float*)d_in[0];
    const float* paras = (const float*)d_in[1];
    if (n_in >= 2 && in_sizes[0] > in_sizes[1]) {  // defensive ordering by size
        data  = (const float*)d_in[1];
        paras = (const float*)d_in[0];
    }
    inv1x1mm_svd_kernel<<<NPOS / POS_PER_BLOCK, 256>>>(data, paras, (float*)d_out);
}